// round 7
// baseline (speedup 1.0000x reference)
#include <cuda_runtime.h>
#include <cuda_bf16.h>
#include <math.h>
#include <stdint.h>

#define BB 4
#define CC 64
#define OO 64
#define DD 2
#define HH 128
#define WW 128
#define HW (HH*WW)
#define QQ (DD*HW)          // 32768 pixels per (b) across depth

// Scratch: offset (B,18,D,H,W) and mask (B,9,D,H,W)
__device__ float g_off[BB*18*DD*HW];
__device__ float g_mask[BB*9*DD*HW];
// Channels-last copy of x: [b][q = d*HW + y*W + x][c]
__device__ float g_xt[(size_t)BB*QQ*CC];
// Prepacked bf16 deform-weight tiles: per tap j, [oc][ch] row-major, hi and lo.
__device__ __nv_bfloat16 g_Bh[9][64*64];
__device__ __nv_bfloat16 g_Bl[9][64*64];
// Prepacked conv3d offset/mask weights: [od][dd*9+tap][32 oc x 64 ch], hi/lo.
__device__ __nv_bfloat16 g_OWh[2][18][32*64];
__device__ __nv_bfloat16 g_OWl[2][18][32*64];

__device__ __forceinline__ uint32_t smem_to_u32(const void* p) {
    uint32_t a;
    asm("{ .reg .u64 t; cvta.to.shared.u64 t, %1; cvt.u32.u64 %0, t; }"
        : "=r"(a) : "l"(p));
    return a;
}

#define LDMATRIX_X4(r0, r1, r2, r3, addr) \
    asm volatile("ldmatrix.sync.aligned.m8n8.x4.shared.b16 {%0,%1,%2,%3}, [%4];" \
        : "=r"(r0), "=r"(r1), "=r"(r2), "=r"(r3) : "r"(addr))

#define MMA_BF16(c, a0, a1, a2, a3, b0, b1) \
    asm volatile("mma.sync.aligned.m16n8k16.row.col.f32.bf16.bf16.f32 " \
        "{%0,%1,%2,%3}, {%4,%5,%6,%7}, {%8,%9}, {%0,%1,%2,%3};" \
        : "+f"((c)[0]), "+f"((c)[1]), "+f"((c)[2]), "+f"((c)[3]) \
        : "r"(a0), "r"(a1), "r"(a2), "r"(a3), "r"(b0), "r"(b1))

#define STS_V4(addr, v0, v1, v2, v3) \
    asm volatile("st.shared.v4.u32 [%0], {%1,%2,%3,%4};" \
        :: "r"(addr), "r"(v0), "r"(v1), "r"(v2), "r"(v3) : "memory")

// Split 8 fp32 -> 4 packed bf16x2 hi + 4 packed bf16x2 lo
__device__ __forceinline__ void cvt_split8(float4 a, float4 b,
                                           uint32_t* hi, uint32_t* lo) {
    float v[8] = {a.x, a.y, a.z, a.w, b.x, b.y, b.z, b.w};
#pragma unroll
    for (int k = 0; k < 4; k++) {
        __nv_bfloat16 h0 = __float2bfloat16(v[2*k]);
        __nv_bfloat16 h1 = __float2bfloat16(v[2*k+1]);
        hi[k] = (uint32_t)__bfloat16_as_ushort(h0)
              | ((uint32_t)__bfloat16_as_ushort(h1) << 16);
        float l0 = v[2*k]   - __bfloat162float(h0);
        float l1 = v[2*k+1] - __bfloat162float(h1);
        asm("cvt.rn.bf16x2.f32 %0, %1, %2;" : "=r"(lo[k]) : "f"(l1), "f"(l0));
    }
}

// ---------------------------------------------------------------------------
// Kernel 0a: pack all weights -> bf16 hi/lo tiles
// ---------------------------------------------------------------------------
__global__ void pack_w_kernel(const float* __restrict__ w0,
                              const float* __restrict__ ow,
                              const float* __restrict__ mw) {
    const int N1 = 9*4096;
    const int N2 = 2*18*2048;
    for (int i = threadIdx.x + blockIdx.x * blockDim.x; i < N1 + N2;
         i += blockDim.x * gridDim.x) {
        if (i < N1) {
            int j = i / 4096;
            int r = i - j*4096;
            int o = r >> 6;
            int c = r & 63;
            float v = w0[(o*CC + c)*9 + j];
            __nv_bfloat16 hb = __float2bfloat16(v);
            g_Bh[j][r] = hb;
            g_Bl[j][r] = __float2bfloat16(v - __bfloat162float(hb));
        } else {
            int k = i - N1;
            int od = k / 36864;
            int r2 = k - od*36864;
            int jj = r2 >> 11;
            int q  = r2 & 2047;
            int o  = q >> 6;
            int c  = q & 63;
            int dd = jj / 9;
            int tap = jj - dd*9;
            int kd = dd + (od == 0 ? 1 : 0);
            float v = 0.f;
            if (o < 18)      v = ow[((o*CC + c)*3 + kd)*9 + tap];
            else if (o < 27) v = mw[(((o-18)*CC + c)*3 + kd)*9 + tap];
            __nv_bfloat16 hb = __float2bfloat16(v);
            g_OWh[od][jj][q] = hb;
            g_OWl[od][jj][q] = __float2bfloat16(v - __bfloat162float(hb));
        }
    }
}

// ---------------------------------------------------------------------------
// Kernel 0b: transpose x (B,C,D,H,W) -> g_xt (B, q=D*H*W, C)
// Grid (QQ/32, CC/32, BB), block (32, 8).
// ---------------------------------------------------------------------------
__global__ void transpose_x_kernel(const float* __restrict__ x) {
    __shared__ float tile[32][33];
    const int b  = blockIdx.z;
    const int c0 = blockIdx.y * 32;
    const int q0 = blockIdx.x * 32;
    const int tx = threadIdx.x;
    const int ty = threadIdx.y;
    const float* src = x + ((size_t)b*CC + c0) * QQ + q0;
#pragma unroll
    for (int i = 0; i < 4; i++)
        tile[ty + i*8][tx] = src[(size_t)(ty + i*8) * QQ + tx];
    __syncthreads();
    float* dst = g_xt + ((size_t)b*QQ + q0) * CC + c0;
#pragma unroll
    for (int i = 0; i < 4; i++)
        dst[(size_t)(ty + i*8) * CC + tx] = tile[tx][ty + i*8];
}

// ---------------------------------------------------------------------------
// Kernel 1: conv3d offset/mask via mma.sync bf16 split-precision.
// Block: 256 threads: thread = (pixel = tid&127, channel-half = tid>>7).
// Grid (128, 2, 4). A: [128 pix][72 halfs] hi+lo. B: [32 oc][72 halfs] hi+lo.
// 8 warps, each owns one 16-row m-tile x all 4 n-tiles.
// ---------------------------------------------------------------------------
#define ASTRIDE_B 144            // bytes per row (72 halfs: 64 data + 8 pad)
#define CV_A_HI   0
#define CV_A_LO   (128*ASTRIDE_B)            // 18432
#define CV_B_HI   (2*128*ASTRIDE_B)          // 36864
#define CV_B_LO   (CV_B_HI + 32*ASTRIDE_B)   // 41472
#define CV_TOTAL  (CV_B_LO + 32*ASTRIDE_B)   // 46080

__global__ __launch_bounds__(256)
void conv3d_mma_kernel(const float* __restrict__ ob,
                       const float* __restrict__ mb)
{
    extern __shared__ char smem[];
    const uint32_t smem_u = smem_to_u32(smem);
    const int tid   = threadIdx.x;
    const int wid   = tid >> 5;
    const int lane  = tid & 31;
    const int pixel = tid & 127;
    const int half  = tid >> 7;
    const int y   = blockIdx.x;
    const int od  = blockIdx.y;
    const int b   = blockIdx.z;

    float acc[4][4];
#pragma unroll
    for (int nt = 0; nt < 4; nt++)
#pragma unroll
        for (int q = 0; q < 4; q++) acc[nt][q] = 0.f;

    const int agrp = lane >> 3;
    const int arow_off = (lane & 7) + ((agrp & 1) << 3);
    const int acol_off = (agrp >> 1) << 4;
    const int brow_off = (lane & 7) + ((agrp >> 1) << 3);
    const int bcol_off = (agrp & 1) << 4;
    const uint32_t arow = (uint32_t)pixel * ASTRIDE_B + (uint32_t)(half*64);

#pragma unroll 1
    for (int jj = 0; jj < 18; jj++) {
        const int dd  = jj / 9;
        const int tap = jj - dd*9;
        const int ky  = tap / 3;
        const int kx  = tap - ky*3;

        // ---- B tile copy: 32 rows x 8 segs = 256 units, one per thread ----
        {
            const uint4* sh = (const uint4*)(g_OWh[od][jj]);
            const uint4* sl = (const uint4*)(g_OWl[od][jj]);
            int row = tid >> 3, seg = tid & 7;
            uint32_t dst = row*ASTRIDE_B + seg*16;
            uint4 vh = sh[tid];
            uint4 vl = sl[tid];
            STS_V4(smem_u + CV_B_HI + dst, vh.x, vh.y, vh.z, vh.w);
            STS_V4(smem_u + CV_B_LO + dst, vl.x, vl.y, vl.z, vl.w);
        }

        // ---- A tile: 32 channels (this half) from channels-last g_xt ----
        const int yin = y - 1 + ky;
        const int xin = pixel - 1 + kx;
        const bool valid = ((unsigned)yin < (unsigned)HH) &&
                           ((unsigned)xin < (unsigned)WW);
        const float* xq = g_xt + ((size_t)b*QQ + dd*HW + yin*WW + xin)*CC
                        + half*32;
        const float4 z4 = make_float4(0.f, 0.f, 0.f, 0.f);
#pragma unroll
        for (int g = 0; g < 4; g++) {     // 8 channels per iteration
            float4 va = valid ? ((const float4*)xq)[2*g]   : z4;
            float4 vb = valid ? ((const float4*)xq)[2*g+1] : z4;
            uint32_t hi[4], lo[4];
            cvt_split8(va, vb, hi, lo);
            uint32_t off = arow + (uint32_t)(g*16);
            STS_V4(smem_u + CV_A_HI + off, hi[0], hi[1], hi[2], hi[3]);
            STS_V4(smem_u + CV_A_LO + off, lo[0], lo[1], lo[2], lo[3]);
        }

        __syncthreads();

        // ---- MMA: warp wid owns m-tile rows [wid*16, wid*16+16) ----
#pragma unroll
        for (int pass = 0; pass < 3; pass++) {
            const uint32_t Abase = smem_u + ((pass == 2) ? CV_A_LO : CV_A_HI);
            const uint32_t Bbase = smem_u + ((pass == 1) ? CV_B_LO : CV_B_HI);
#pragma unroll
            for (int ks = 0; ks < 4; ks++) {
                uint32_t a0, a1, a2, a3;
                {
                    uint32_t addr = Abase
                        + (uint32_t)(wid*16 + arow_off) * ASTRIDE_B
                        + (uint32_t)(ks*32 + acol_off);
                    LDMATRIX_X4(a0, a1, a2, a3, addr);
                }
#pragma unroll
                for (int np = 0; np < 2; np++) {
                    uint32_t b0, b1, b2, b3;
                    uint32_t addr = Bbase
                        + (uint32_t)(np*16 + brow_off) * ASTRIDE_B
                        + (uint32_t)(ks*32 + bcol_off);
                    LDMATRIX_X4(b0, b1, b2, b3, addr);
                    MMA_BF16(acc[np*2],   a0, a1, a2, a3, b0, b1);
                    MMA_BF16(acc[np*2+1], a0, a1, a2, a3, b2, b3);
                }
            }
        }
        __syncthreads();
    }

    // ---- epilogue: bias + sigmoid, write g_off / g_mask ----
    {
        int prow = wid*16 + (lane >> 2);
#pragma unroll
        for (int nt = 0; nt < 4; nt++) {
            int oc0 = nt*8 + 2*(lane & 3);
#pragma unroll
            for (int q = 0; q < 4; q++) {
                int oc = oc0 + (q & 1);
                int p  = prow + ((q >> 1) << 3);
                float v = acc[nt][q];
                int pixo = y*WW + p;
                if (oc < 18) {
                    g_off[((b*18 + oc)*DD + od)*HW + pixo] = v + ob[oc];
                } else if (oc < 27) {
                    float t = v + mb[oc - 18];
                    g_mask[((b*9 + oc - 18)*DD + od)*HW + pixo] =
                        2.f / (1.f + expf(-t));
                }
            }
        }
    }
}

// ---------------------------------------------------------------------------
// Kernel 2: deformable conv via mma.sync bf16 split-precision.
// Block: 256 threads: (pixel = tid&127, channel-half = tid>>7). Grid (128,2,4).
// Gathers from channels-last g_xt. 8 warps, each one 16-row m-tile x 8 n-tiles.
// ---------------------------------------------------------------------------
#define SM_A_HI   0
#define SM_A_LO   (128*ASTRIDE_B)            // 18432
#define SM_B_HI   (2*128*ASTRIDE_B)          // 36864
#define SM_B_LO   (SM_B_HI + 64*ASTRIDE_B)   // 46080
#define SM_TOTAL  (SM_B_LO + 64*ASTRIDE_B)   // 55296

__global__ __launch_bounds__(256)
void deform_mma_kernel(float* __restrict__ out)
{
    extern __shared__ char smem[];
    const uint32_t smem_u = smem_to_u32(smem);
    const int tid   = threadIdx.x;
    const int wid   = tid >> 5;
    const int lane  = tid & 31;
    const int pixel = tid & 127;
    const int half  = tid >> 7;
    const int y   = blockIdx.x;
    const int d   = blockIdx.y;
    const int b   = blockIdx.z;
    const int pix = y*WW + pixel;

    float acc[8][4];
#pragma unroll
    for (int nt = 0; nt < 8; nt++)
#pragma unroll
        for (int q = 0; q < 4; q++) acc[nt][q] = 0.f;

    const float* xtb = g_xt + ((size_t)b*QQ + d*HW)*CC + half*32;

    const int agrp = lane >> 3;
    const int arow_off = (lane & 7) + ((agrp & 1) << 3);
    const int acol_off = (agrp >> 1) << 4;
    const int brow_off = (lane & 7) + ((agrp >> 1) << 3);
    const int bcol_off = (agrp & 1) << 4;
    const uint32_t arow = (uint32_t)pixel * ASTRIDE_B + (uint32_t)(half*64);

#pragma unroll 1
    for (int j = 0; j < 9; j++) {
        // ---- B tile copy: 64 rows x 8 segs = 512 units ----
        {
            const uint4* sh = (const uint4*)(g_Bh[j]);
            const uint4* sl = (const uint4*)(g_Bl[j]);
#pragma unroll
            for (int it = 0; it < 2; it++) {
                int u = tid + 256*it;
                int row = u >> 3, seg = u & 7;
                uint32_t dst = row*ASTRIDE_B + seg*16;
                uint4 vh = sh[u];
                uint4 vl = sl[u];
                STS_V4(smem_u + SM_B_HI + dst, vh.x, vh.y, vh.z, vh.w);
                STS_V4(smem_u + SM_B_LO + dst, vl.x, vl.y, vl.z, vl.w);
            }
        }

        // ---- per-pixel sampling setup ----
        float dy = g_off[((b*18 + 2*j    )*DD + d)*HW + pix];
        float dx = g_off[((b*18 + 2*j + 1)*DD + d)*HW + pix];
        float m  = g_mask[((b*9 + j)*DD + d)*HW + pix];
        float py = (float)(y     - 1 + j/3) + dy;
        float px = (float)(pixel - 1 + j%3) + dx;
        float fy = floorf(py), fx = floorf(px);
        float ly = py - fy,    lx = px - fx;
        float hy = 1.f - ly,   hx = 1.f - lx;
        int iy0 = (int)fy, ix0 = (int)fx;
        int iy1 = iy0 + 1, ix1 = ix0 + 1;
        bool vy0 = ((unsigned)iy0 < (unsigned)HH);
        bool vy1 = ((unsigned)iy1 < (unsigned)HH);
        bool vx0 = ((unsigned)ix0 < (unsigned)WW);
        bool vx1 = ((unsigned)ix1 < (unsigned)WW);
        float a00 = (vy0 && vx0) ? hy*hx*m : 0.f;
        float a01 = (vy0 && vx1) ? hy*lx*m : 0.f;
        float a10 = (vy1 && vx0) ? ly*hx*m : 0.f;
        float a11 = (vy1 && vx1) ? ly*lx*m : 0.f;
        int yr0 = min(max(iy0, 0), HH-1)*WW;
        int yr1 = min(max(iy1, 0), HH-1)*WW;
        int xr0 = min(max(ix0, 0), WW-1);
        int xr1 = min(max(ix1, 0), WW-1);
        const float4* c00 = (const float4*)(xtb + (size_t)(yr0 + xr0)*CC);
        const float4* c01 = (const float4*)(xtb + (size_t)(yr0 + xr1)*CC);
        const float4* c10 = (const float4*)(xtb + (size_t)(yr1 + xr0)*CC);
        const float4* c11 = (const float4*)(xtb + (size_t)(yr1 + xr1)*CC);

        // ---- A tile: 32 channels (this half), bilinear from 4 corners ----
#pragma unroll
        for (int g = 0; g < 4; g++) {   // 8 channels per iteration
            float4 va, vb;
#pragma unroll
            for (int h2 = 0; h2 < 2; h2++) {
                float4 p00 = c00[2*g + h2];
                float4 p01 = c01[2*g + h2];
                float4 p10 = c10[2*g + h2];
                float4 p11 = c11[2*g + h2];
                float4 r;
                r.x = a00*p00.x + a01*p01.x + a10*p10.x + a11*p11.x;
                r.y = a00*p00.y + a01*p01.y + a10*p10.y + a11*p11.y;
                r.z = a00*p00.z + a01*p01.z + a10*p10.z + a11*p11.z;
                r.w = a00*p00.w + a01*p01.w + a10*p10.w + a11*p11.w;
                if (h2 == 0) va = r; else vb = r;
            }
            uint32_t hi[4], lo[4];
            cvt_split8(va, vb, hi, lo);
            uint32_t off = arow + (uint32_t)(g*16);
            STS_V4(smem_u + SM_A_HI + off, hi[0], hi[1], hi[2], hi[3]);
            STS_V4(smem_u + SM_A_LO + off, lo[0], lo[1], lo[2], lo[3]);
        }

        __syncthreads();

        // ---- MMA: warp wid owns m-tile rows [wid*16, wid*16+16) ----
#pragma unroll
        for (int pass = 0; pass < 3; pass++) {
            const uint32_t Abase = smem_u + ((pass == 2) ? SM_A_LO : SM_A_HI);
            const uint32_t Bbase = smem_u + ((pass == 1) ? SM_B_LO : SM_B_HI);
#pragma unroll
            for (int ks = 0; ks < 4; ks++) {
                uint32_t a0, a1, a2, a3;
                {
                    uint32_t addr = Abase
                        + (uint32_t)(wid*16 + arow_off) * ASTRIDE_B
                        + (uint32_t)(ks*32 + acol_off);
                    LDMATRIX_X4(a0, a1, a2, a3, addr);
                }
#pragma unroll
                for (int np = 0; np < 4; np++) {
                    uint32_t b0, b1, b2, b3;
                    uint32_t addr = Bbase
                        + (uint32_t)(np*16 + brow_off) * ASTRIDE_B
                        + (uint32_t)(ks*32 + bcol_off);
                    LDMATRIX_X4(b0, b1, b2, b3, addr);
                    MMA_BF16(acc[np*2],   a0, a1, a2, a3, b0, b1);
                    MMA_BF16(acc[np*2+1], a0, a1, a2, a3, b2, b3);
                }
            }
        }
        __syncthreads();
    }

    // ---- epilogue ----
    {
        int xr = wid*16 + (lane >> 2);
        float* op0 = out + ((size_t)b*OO*DD + d)*HW + y*WW + xr;
#pragma unroll
        for (int nt = 0; nt < 8; nt++) {
            int oc = nt*8 + 2*(lane & 3);
            op0[(size_t)(oc  )*DD*HW    ] = acc[nt][0];
            op0[(size_t)(oc+1)*DD*HW    ] = acc[nt][1];
            op0[(size_t)(oc  )*DD*HW + 8] = acc[nt][2];
            op0[(size_t)(oc+1)*DD*HW + 8] = acc[nt][3];
        }
    }
}

// ---------------------------------------------------------------------------
// Launch
// ---------------------------------------------------------------------------
extern "C" void kernel_launch(void* const* d_in, const int* in_sizes, int n_in,
                              void* d_out, int out_size)
{
    const float* x  = (const float*)d_in[0];
    const float* ow = (const float*)d_in[1];
    const float* ob = (const float*)d_in[2];
    const float* mw = (const float*)d_in[3];
    const float* mb = (const float*)d_in[4];
    const float* w0 = (const float*)d_in[5];
    float* out = (float*)d_out;

    cudaFuncSetAttribute(deform_mma_kernel,
                         cudaFuncAttributeMaxDynamicSharedMemorySize, SM_TOTAL);
    cudaFuncSetAttribute(conv3d_mma_kernel,
                         cudaFuncAttributeMaxDynamicSharedMemorySize, CV_TOTAL);

    dim3 grid(HH, DD, BB);
    dim3 tgrid(QQ/32, CC/32, BB);
    pack_w_kernel<<<120, 256>>>(w0, ow, mw);
    transpose_x_kernel<<<tgrid, dim3(32, 8)>>>(x);
    conv3d_mma_kernel<<<grid, 256, CV_TOTAL>>>(ob, mb);
    deform_mma_kernel<<<grid, 256, SM_TOTAL>>>(out);
}

// round 9
// speedup vs baseline: 1.8422x; 1.8422x over previous
#include <cuda_runtime.h>
#include <cuda_bf16.h>
#include <math.h>
#include <stdint.h>

#define BB 4
#define CC 64
#define OO 64
#define DD 2
#define HH 128
#define WW 128
#define HW (HH*WW)

// Scratch: offset (B,18,D,H,W) and mask (B,9,D,H,W)
__device__ float g_off[BB*18*DD*HW];
__device__ float g_mask[BB*9*DD*HW];
// Prepacked bf16 deform-weight tiles per tap j: 64 rows(oc) x 128B, XOR-swizzled.
__device__ __nv_bfloat16 g_Bh[9][64*64];
__device__ __nv_bfloat16 g_Bl[9][64*64];
// Prepacked conv3d offset/mask weights: [od][dd*9+tap][32 oc x 64 ch], swizzled.
__device__ __nv_bfloat16 g_OWh[2][18][32*64];
__device__ __nv_bfloat16 g_OWl[2][18][32*64];

__device__ __forceinline__ uint32_t smem_to_u32(const void* p) {
    uint32_t a;
    asm("{ .reg .u64 t; cvta.to.shared.u64 t, %1; cvt.u32.u64 %0, t; }"
        : "=r"(a) : "l"(p));
    return a;
}

#define LDMATRIX_X4(r0, r1, r2, r3, addr) \
    asm volatile("ldmatrix.sync.aligned.m8n8.x4.shared.b16 {%0,%1,%2,%3}, [%4];" \
        : "=r"(r0), "=r"(r1), "=r"(r2), "=r"(r3) : "r"(addr))

#define MMA_BF16(c, a0, a1, a2, a3, b0, b1) \
    asm volatile("mma.sync.aligned.m16n8k16.row.col.f32.bf16.bf16.f32 " \
        "{%0,%1,%2,%3}, {%4,%5,%6,%7}, {%8,%9}, {%0,%1,%2,%3};" \
        : "+f"((c)[0]), "+f"((c)[1]), "+f"((c)[2]), "+f"((c)[3]) \
        : "r"(a0), "r"(a1), "r"(a2), "r"(a3), "r"(b0), "r"(b1))

#define STS_V4(addr, v0, v1, v2, v3) \
    asm volatile("st.shared.v4.u32 [%0], {%1,%2,%3,%4};" \
        :: "r"(addr), "r"(v0), "r"(v1), "r"(v2), "r"(v3) : "memory")

// Split 8 fp32 -> 4 packed bf16x2 hi + 4 packed bf16x2 lo
__device__ __forceinline__ void cvt_split8(const float* v,
                                           uint32_t* hi, uint32_t* lo) {
#pragma unroll
    for (int k = 0; k < 4; k++) {
        __nv_bfloat16 h0 = __float2bfloat16(v[2*k]);
        __nv_bfloat16 h1 = __float2bfloat16(v[2*k+1]);
        hi[k] = (uint32_t)__bfloat16_as_ushort(h0)
              | ((uint32_t)__bfloat16_as_ushort(h1) << 16);
        float l0 = v[2*k]   - __bfloat162float(h0);
        float l1 = v[2*k+1] - __bfloat162float(h1);
        asm("cvt.rn.bf16x2.f32 %0, %1, %2;" : "=r"(lo[k]) : "f"(l1), "f"(l0));
    }
}

// Swizzled halfword index within a 64-halfword (128B) row: row r, channel c.
// byte layout: r*128 + ( (c>>3 chunk)*16 ^ ((r&7)*16) ) + (c&7)*2
__device__ __forceinline__ int sw_idx(int r, int c) {
    return r*64 + (((c >> 3) ^ (r & 7)) << 3) + (c & 7);
}

// ---------------------------------------------------------------------------
// Kernel 0: pack all weights -> bf16 hi/lo swizzled tiles
// ---------------------------------------------------------------------------
__global__ void pack_w_kernel(const float* __restrict__ w0,
                              const float* __restrict__ ow,
                              const float* __restrict__ mw) {
    const int N1 = 9*4096;
    const int N2 = 2*18*2048;
    for (int i = threadIdx.x + blockIdx.x * blockDim.x; i < N1 + N2;
         i += blockDim.x * gridDim.x) {
        if (i < N1) {
            int j = i / 4096;
            int r = i - j*4096;
            int o = r >> 6;
            int c = r & 63;
            float v = w0[(o*CC + c)*9 + j];
            __nv_bfloat16 hb = __float2bfloat16(v);
            int s = sw_idx(o, c);
            g_Bh[j][s] = hb;
            g_Bl[j][s] = __float2bfloat16(v - __bfloat162float(hb));
        } else {
            int k = i - N1;
            int od = k / 36864;
            int r2 = k - od*36864;
            int jj = r2 >> 11;
            int q  = r2 & 2047;
            int o  = q >> 6;
            int c  = q & 63;
            int dd = jj / 9;
            int tap = jj - dd*9;
            int kd = dd + (od == 0 ? 1 : 0);
            float v = 0.f;
            if (o < 18)      v = ow[((o*CC + c)*3 + kd)*9 + tap];
            else if (o < 27) v = mw[(((o-18)*CC + c)*3 + kd)*9 + tap];
            __nv_bfloat16 hb = __float2bfloat16(v);
            int s = sw_idx(o, c);
            g_OWh[od][jj][s] = hb;
            g_OWl[od][jj][s] = __float2bfloat16(v - __bfloat162float(hb));
        }
    }
}

// ---------------------------------------------------------------------------
// Kernel 1: conv3d offset/mask via mma.sync bf16 split-precision.
// 256 threads: (pixel = tid&127, half = tid>>7 -> channels [32h,32h+32)).
// Grid (128, 2, 4). A: 128 rows x 128B swizzled, hi+lo. B: 32 rows x 128B.
// 8 warps, each one 16-row m-tile x 4 n-tiles.
// ---------------------------------------------------------------------------
#define CV_A_HI   0
#define CV_A_LO   16384
#define CV_B_HI   32768
#define CV_B_LO   36864
#define CV_TOTAL  40960

__global__ __launch_bounds__(256)
void conv3d_mma_kernel(const float* __restrict__ x,
                       const float* __restrict__ ob,
                       const float* __restrict__ mb)
{
    extern __shared__ char smem[];
    const uint32_t smem_u = smem_to_u32(smem);
    const int tid   = threadIdx.x;
    const int wid   = tid >> 5;
    const int lane  = tid & 31;
    const int pixel = tid & 127;
    const int half  = tid >> 7;
    const int y   = blockIdx.x;
    const int od  = blockIdx.y;
    const int b   = blockIdx.z;

    float acc[4][4];
#pragma unroll
    for (int nt = 0; nt < 4; nt++)
#pragma unroll
        for (int q = 0; q < 4; q++) acc[nt][q] = 0.f;

    const int agrp = lane >> 3;
    const int arow_off = (lane & 7) + ((agrp & 1) << 3);
    const int achunk   = (agrp >> 1);            // 0/1 (16B chunk within k-step)
    const int brow_off = (lane & 7) + ((agrp >> 1) << 3);
    const int bchunk   = (agrp & 1);
    const uint32_t arowb = (uint32_t)pixel * 128;
    const int swrow = pixel & 7;

#pragma unroll 1
    for (int jj = 0; jj < 18; jj++) {
        const int dd  = jj / 9;
        const int tap = jj - dd*9;
        const int ky  = tap / 3;
        const int kx  = tap - ky*3;

        // ---- B tile copy: 32 rows x 8 chunks = 256 units, 1/thread ----
        {
            const uint4* sh = (const uint4*)(g_OWh[od][jj]);
            const uint4* sl = (const uint4*)(g_OWl[od][jj]);
            uint4 vh = sh[tid];
            uint4 vl = sl[tid];
            uint32_t dst = (uint32_t)tid * 16;
            STS_V4(smem_u + CV_B_HI + dst, vh.x, vh.y, vh.z, vh.w);
            STS_V4(smem_u + CV_B_LO + dst, vl.x, vl.y, vl.z, vl.w);
        }

        // ---- A tile: 32 channels (this half), shifted coalesced reads ----
        const int yin = y - 1 + ky;
        const int xin = pixel - 1 + kx;
        const bool valid = ((unsigned)yin < (unsigned)HH) &&
                           ((unsigned)xin < (unsigned)WW);
        const float* xp0 = x + ((size_t)(b*CC)*DD + dd)*HW + yin*WW + xin;
#pragma unroll 2
        for (int g = 0; g < 4; g++) {        // 8 channels per g
            float v[8];
#pragma unroll
            for (int k = 0; k < 8; k++) {
                int c = half*32 + g*8 + k;
                v[k] = valid ? xp0[(size_t)c*(DD*HW)] : 0.f;
            }
            uint32_t hi[4], lo[4];
            cvt_split8(v, hi, lo);
            uint32_t coff = (uint32_t)(((half*4 + g) ^ swrow) << 4);
            STS_V4(smem_u + CV_A_HI + arowb + coff, hi[0], hi[1], hi[2], hi[3]);
            STS_V4(smem_u + CV_A_LO + arowb + coff, lo[0], lo[1], lo[2], lo[3]);
        }

        __syncthreads();

        // ---- MMA ----
#pragma unroll
        for (int pass = 0; pass < 3; pass++) {
            const uint32_t Abase = smem_u + ((pass == 2) ? CV_A_LO : CV_A_HI);
            const uint32_t Bbase = smem_u + ((pass == 1) ? CV_B_LO : CV_B_HI);
#pragma unroll
            for (int ks = 0; ks < 4; ks++) {
                uint32_t a0, a1, a2, a3;
                {
                    int rr = wid*16 + arow_off;
                    uint32_t addr = Abase + (uint32_t)rr*128
                        + (uint32_t)((((ks*2 + achunk) ^ (rr & 7)) << 4));
                    LDMATRIX_X4(a0, a1, a2, a3, addr);
                }
#pragma unroll
                for (int np = 0; np < 2; np++) {
                    uint32_t b0, b1, b2, b3;
                    int nn = np*16 + brow_off;
                    uint32_t addr = Bbase + (uint32_t)nn*128
                        + (uint32_t)((((ks*2 + bchunk) ^ (nn & 7)) << 4));
                    LDMATRIX_X4(b0, b1, b2, b3, addr);
                    MMA_BF16(acc[np*2],   a0, a1, a2, a3, b0, b1);
                    MMA_BF16(acc[np*2+1], a0, a1, a2, a3, b2, b3);
                }
            }
        }
        __syncthreads();
    }

    // ---- epilogue: bias + sigmoid, write g_off / g_mask ----
    {
        int prow = wid*16 + (lane >> 2);
#pragma unroll
        for (int nt = 0; nt < 4; nt++) {
            int oc0 = nt*8 + 2*(lane & 3);
#pragma unroll
            for (int q = 0; q < 4; q++) {
                int oc = oc0 + (q & 1);
                int p  = prow + ((q >> 1) << 3);
                float v = acc[nt][q];
                int pixo = y*WW + p;
                if (oc < 18) {
                    g_off[((b*18 + oc)*DD + od)*HW + pixo] = v + ob[oc];
                } else if (oc < 27) {
                    float t = v + mb[oc - 18];
                    g_mask[((b*9 + oc - 18)*DD + od)*HW + pixo] =
                        2.f / (1.f + expf(-t));
                }
            }
        }
    }
}

// ---------------------------------------------------------------------------
// Kernel 2: deformable conv via mma.sync bf16 split-precision.
// 256 threads: (pixel, half). Grid (128, 2, 4). Channel-major coalesced gathers.
// 8 warps, each one 16-row m-tile x 8 n-tiles.
// ---------------------------------------------------------------------------
#define SM_A_HI   0
#define SM_A_LO   16384
#define SM_B_HI   32768
#define SM_B_LO   40960
#define SM_TOTAL  49152

__global__ __launch_bounds__(256)
void deform_mma_kernel(const float* __restrict__ x, float* __restrict__ out)
{
    extern __shared__ char smem[];
    const uint32_t smem_u = smem_to_u32(smem);
    const int tid   = threadIdx.x;
    const int wid   = tid >> 5;
    const int lane  = tid & 31;
    const int pixel = tid & 127;
    const int half  = tid >> 7;
    const int y   = blockIdx.x;
    const int d   = blockIdx.y;
    const int b   = blockIdx.z;
    const int pix = y*WW + pixel;

    float acc[8][4];
#pragma unroll
    for (int nt = 0; nt < 8; nt++)
#pragma unroll
        for (int q = 0; q < 4; q++) acc[nt][q] = 0.f;

    const float* xbase = x + ((size_t)b*CC*DD + d) * HW;

    const int agrp = lane >> 3;
    const int arow_off = (lane & 7) + ((agrp & 1) << 3);
    const int achunk   = (agrp >> 1);
    const int brow_off = (lane & 7) + ((agrp >> 1) << 3);
    const int bchunk   = (agrp & 1);
    const uint32_t arowb = (uint32_t)pixel * 128;
    const int swrow = pixel & 7;

#pragma unroll 1
    for (int j = 0; j < 9; j++) {
        // ---- B tile copy: 64 rows x 8 chunks = 512 units, 2/thread ----
        {
            const uint4* sh = (const uint4*)(g_Bh[j]);
            const uint4* sl = (const uint4*)(g_Bl[j]);
#pragma unroll
            for (int it = 0; it < 2; it++) {
                int u = tid + 256*it;
                uint4 vh = sh[u];
                uint4 vl = sl[u];
                uint32_t dst = (uint32_t)u * 16;
                STS_V4(smem_u + SM_B_HI + dst, vh.x, vh.y, vh.z, vh.w);
                STS_V4(smem_u + SM_B_LO + dst, vl.x, vl.y, vl.z, vl.w);
            }
        }

        // ---- per-pixel sampling setup ----
        float dy = g_off[((b*18 + 2*j    )*DD + d)*HW + pix];
        float dx = g_off[((b*18 + 2*j + 1)*DD + d)*HW + pix];
        float m  = g_mask[((b*9 + j)*DD + d)*HW + pix];
        float py = (float)(y     - 1 + j/3) + dy;
        float px = (float)(pixel - 1 + j%3) + dx;
        float fy = floorf(py), fx = floorf(px);
        float ly = py - fy,    lx = px - fx;
        float hy = 1.f - ly,   hx = 1.f - lx;
        int iy0 = (int)fy, ix0 = (int)fx;
        int iy1 = iy0 + 1, ix1 = ix0 + 1;
        bool vy0 = ((unsigned)iy0 < (unsigned)HH);
        bool vy1 = ((unsigned)iy1 < (unsigned)HH);
        bool vx0 = ((unsigned)ix0 < (unsigned)WW);
        bool vx1 = ((unsigned)ix1 < (unsigned)WW);
        float a00 = (vy0 && vx0) ? hy*hx*m : 0.f;
        float a01 = (vy0 && vx1) ? hy*lx*m : 0.f;
        float a10 = (vy1 && vx0) ? ly*hx*m : 0.f;
        float a11 = (vy1 && vx1) ? ly*lx*m : 0.f;
        int yr0 = min(max(iy0, 0), HH-1)*WW;
        int yr1 = min(max(iy1, 0), HH-1)*WW;
        int xr0 = min(max(ix0, 0), WW-1);
        int xr1 = min(max(ix1, 0), WW-1);
        int o00 = yr0 + xr0, o01 = yr0 + xr1;
        int o10 = yr1 + xr0, o11 = yr1 + xr1;

        // ---- A tile: 32 channels (this half), coalesced channel-major ----
#pragma unroll 2
        for (int g = 0; g < 4; g++) {        // 8 channels per g
            float v[8];
#pragma unroll
            for (int k = 0; k < 8; k++) {
                const float* xp = xbase + (size_t)(half*32 + g*8 + k)*(DD*HW);
                v[k] = a00*xp[o00] + a01*xp[o01] + a10*xp[o10] + a11*xp[o11];
            }
            uint32_t hi[4], lo[4];
            cvt_split8(v, hi, lo);
            uint32_t coff = (uint32_t)(((half*4 + g) ^ swrow) << 4);
            STS_V4(smem_u + SM_A_HI + arowb + coff, hi[0], hi[1], hi[2], hi[3]);
            STS_V4(smem_u + SM_A_LO + arowb + coff, lo[0], lo[1], lo[2], lo[3]);
        }

        __syncthreads();

        // ---- MMA ----
#pragma unroll
        for (int pass = 0; pass < 3; pass++) {
            const uint32_t Abase = smem_u + ((pass == 2) ? SM_A_LO : SM_A_HI);
            const uint32_t Bbase = smem_u + ((pass == 1) ? SM_B_LO : SM_B_HI);
#pragma unroll
            for (int ks = 0; ks < 4; ks++) {
                uint32_t a0, a1, a2, a3;
                {
                    int rr = wid*16 + arow_off;
                    uint32_t addr = Abase + (uint32_t)rr*128
                        + (uint32_t)((((ks*2 + achunk) ^ (rr & 7)) << 4));
                    LDMATRIX_X4(a0, a1, a2, a3, addr);
                }
#pragma unroll
                for (int np = 0; np < 4; np++) {
                    uint32_t b0, b1, b2, b3;
                    int nn = np*16 + brow_off;
                    uint32_t addr = Bbase + (uint32_t)nn*128
                        + (uint32_t)((((ks*2 + bchunk) ^ (nn & 7)) << 4));
                    LDMATRIX_X4(b0, b1, b2, b3, addr);
                    MMA_BF16(acc[np*2],   a0, a1, a2, a3, b0, b1);
                    MMA_BF16(acc[np*2+1], a0, a1, a2, a3, b2, b3);
                }
            }
        }
        __syncthreads();
    }

    // ---- epilogue ----
    {
        int xr = wid*16 + (lane >> 2);
        float* op0 = out + ((size_t)b*OO*DD + d)*HW + y*WW + xr;
#pragma unroll
        for (int nt = 0; nt < 8; nt++) {
            int oc = nt*8 + 2*(lane & 3);
            op0[(size_t)(oc  )*DD*HW    ] = acc[nt][0];
            op0[(size_t)(oc+1)*DD*HW    ] = acc[nt][1];
            op0[(size_t)(oc  )*DD*HW + 8] = acc[nt][2];
            op0[(size_t)(oc+1)*DD*HW + 8] = acc[nt][3];
        }
    }
}

// ---------------------------------------------------------------------------
// Launch
// ---------------------------------------------------------------------------
extern "C" void kernel_launch(void* const* d_in, const int* in_sizes, int n_in,
                              void* d_out, int out_size)
{
    const float* x  = (const float*)d_in[0];
    const float* ow = (const float*)d_in[1];
    const float* ob = (const float*)d_in[2];
    const float* mw = (const float*)d_in[3];
    const float* mb = (const float*)d_in[4];
    const float* w0 = (const float*)d_in[5];
    float* out = (float*)d_out;

    cudaFuncSetAttribute(deform_mma_kernel,
                         cudaFuncAttributeMaxDynamicSharedMemorySize, SM_TOTAL);
    cudaFuncSetAttribute(conv3d_mma_kernel,
                         cudaFuncAttributeMaxDynamicSharedMemorySize, CV_TOTAL);

    dim3 grid(HH, DD, BB);
    pack_w_kernel<<<120, 256>>>(w0, ow, mw);
    conv3d_mma_kernel<<<grid, 256, CV_TOTAL>>>(x, ob, mb);
    deform_mma_kernel<<<grid, 256, SM_TOTAL>>>(x, out);
}

// round 10
// speedup vs baseline: 1.9092x; 1.0364x over previous
#include <cuda_runtime.h>
#include <cuda_bf16.h>
#include <math.h>
#include <stdint.h>

#define BB 4
#define CC 64
#define OO 64
#define DD 2
#define HH 128
#define WW 128
#define HW (HH*WW)

// Scratch: offset (B,18,D,H,W) and mask (B,9,D,H,W)
__device__ float g_off[BB*18*DD*HW];
__device__ float g_mask[BB*9*DD*HW];
// Prepacked bf16 deform-weight tiles per tap j: 64 rows(oc) x 128B, XOR-swizzled.
__device__ __nv_bfloat16 g_Bh[9][64*64];
__device__ __nv_bfloat16 g_Bl[9][64*64];
// Prepacked conv3d offset/mask weights: [od][dd*9+tap][32 oc x 64 ch], swizzled.
__device__ __nv_bfloat16 g_OWh[2][18][32*64];
__device__ __nv_bfloat16 g_OWl[2][18][32*64];

__device__ __forceinline__ uint32_t smem_to_u32(const void* p) {
    uint32_t a;
    asm("{ .reg .u64 t; cvta.to.shared.u64 t, %1; cvt.u32.u64 %0, t; }"
        : "=r"(a) : "l"(p));
    return a;
}

#define LDMATRIX_X4(r0, r1, r2, r3, addr) \
    asm volatile("ldmatrix.sync.aligned.m8n8.x4.shared.b16 {%0,%1,%2,%3}, [%4];" \
        : "=r"(r0), "=r"(r1), "=r"(r2), "=r"(r3) : "r"(addr))

#define MMA_BF16(c, a0, a1, a2, a3, b0, b1) \
    asm volatile("mma.sync.aligned.m16n8k16.row.col.f32.bf16.bf16.f32 " \
        "{%0,%1,%2,%3}, {%4,%5,%6,%7}, {%8,%9}, {%0,%1,%2,%3};" \
        : "+f"((c)[0]), "+f"((c)[1]), "+f"((c)[2]), "+f"((c)[3]) \
        : "r"(a0), "r"(a1), "r"(a2), "r"(a3), "r"(b0), "r"(b1))

#define STS_V4(addr, v0, v1, v2, v3) \
    asm volatile("st.shared.v4.u32 [%0], {%1,%2,%3,%4};" \
        :: "r"(addr), "r"(v0), "r"(v1), "r"(v2), "r"(v3) : "memory")

// Split 8 fp32 -> 4 packed bf16x2 hi + 4 packed bf16x2 lo
__device__ __forceinline__ void cvt_split8(const float* v,
                                           uint32_t* hi, uint32_t* lo) {
#pragma unroll
    for (int k = 0; k < 4; k++) {
        __nv_bfloat16 h0 = __float2bfloat16(v[2*k]);
        __nv_bfloat16 h1 = __float2bfloat16(v[2*k+1]);
        hi[k] = (uint32_t)__bfloat16_as_ushort(h0)
              | ((uint32_t)__bfloat16_as_ushort(h1) << 16);
        float l0 = v[2*k]   - __bfloat162float(h0);
        float l1 = v[2*k+1] - __bfloat162float(h1);
        asm("cvt.rn.bf16x2.f32 %0, %1, %2;" : "=r"(lo[k]) : "f"(l1), "f"(l0));
    }
}

// Swizzled halfword index within a 64-halfword (128B) row: row r, channel c.
__device__ __forceinline__ int sw_idx(int r, int c) {
    return r*64 + (((c >> 3) ^ (r & 7)) << 3) + (c & 7);
}

// ---------------------------------------------------------------------------
// Kernel 0: pack all weights -> bf16 hi/lo swizzled tiles
// ---------------------------------------------------------------------------
__global__ void pack_w_kernel(const float* __restrict__ w0,
                              const float* __restrict__ ow,
                              const float* __restrict__ mw) {
    const int N1 = 9*4096;
    const int N2 = 2*18*2048;
    for (int i = threadIdx.x + blockIdx.x * blockDim.x; i < N1 + N2;
         i += blockDim.x * gridDim.x) {
        if (i < N1) {
            int j = i / 4096;
            int r = i - j*4096;
            int o = r >> 6;
            int c = r & 63;
            float v = w0[(o*CC + c)*9 + j];
            __nv_bfloat16 hb = __float2bfloat16(v);
            int s = sw_idx(o, c);
            g_Bh[j][s] = hb;
            g_Bl[j][s] = __float2bfloat16(v - __bfloat162float(hb));
        } else {
            int k = i - N1;
            int od = k / 36864;
            int r2 = k - od*36864;
            int jj = r2 >> 11;
            int q  = r2 & 2047;
            int o  = q >> 6;
            int c  = q & 63;
            int dd = jj / 9;
            int tap = jj - dd*9;
            int kd = dd + (od == 0 ? 1 : 0);
            float v = 0.f;
            if (o < 18)      v = ow[((o*CC + c)*3 + kd)*9 + tap];
            else if (o < 27) v = mw[(((o-18)*CC + c)*3 + kd)*9 + tap];
            __nv_bfloat16 hb = __float2bfloat16(v);
            int s = sw_idx(o, c);
            g_OWh[od][jj][s] = hb;
            g_OWl[od][jj][s] = __float2bfloat16(v - __bfloat162float(hb));
        }
    }
}

// ---------------------------------------------------------------------------
// Kernel 1: conv3d offset/mask via mma.sync bf16 split-precision.
// 256 threads, 2 CTAs/SM. (pixel = tid&127, half = tid>>7). Grid (128, 2, 4).
// ---------------------------------------------------------------------------
#define CV_A_HI   0
#define CV_A_LO   16384
#define CV_B_HI   32768
#define CV_B_LO   36864
#define CV_TOTAL  40960

__global__ __launch_bounds__(256, 2)
void conv3d_mma_kernel(const float* __restrict__ x,
                       const float* __restrict__ ob,
                       const float* __restrict__ mb)
{
    extern __shared__ char smem[];
    const uint32_t smem_u = smem_to_u32(smem);
    const int tid   = threadIdx.x;
    const int wid   = tid >> 5;
    const int lane  = tid & 31;
    const int pixel = tid & 127;
    const int half  = tid >> 7;
    const int y   = blockIdx.x;
    const int od  = blockIdx.y;
    const int b   = blockIdx.z;

    float acc[4][4];
#pragma unroll
    for (int nt = 0; nt < 4; nt++)
#pragma unroll
        for (int q = 0; q < 4; q++) acc[nt][q] = 0.f;

    const int agrp = lane >> 3;
    const int arow_off = (lane & 7) + ((agrp & 1) << 3);
    const int achunk   = (agrp >> 1);
    const int brow_off = (lane & 7) + ((agrp >> 1) << 3);
    const int bchunk   = (agrp & 1);
    const uint32_t arowb = (uint32_t)pixel * 128;
    const int swrow = pixel & 7;

#pragma unroll 1
    for (int jj = 0; jj < 18; jj++) {
        const int dd  = jj / 9;
        const int tap = jj - dd*9;
        const int ky  = tap / 3;
        const int kx  = tap - ky*3;

        // ---- B tile copy ----
        {
            const uint4* sh = (const uint4*)(g_OWh[od][jj]);
            const uint4* sl = (const uint4*)(g_OWl[od][jj]);
            uint4 vh = sh[tid];
            uint4 vl = sl[tid];
            uint32_t dst = (uint32_t)tid * 16;
            STS_V4(smem_u + CV_B_HI + dst, vh.x, vh.y, vh.z, vh.w);
            STS_V4(smem_u + CV_B_LO + dst, vl.x, vl.y, vl.z, vl.w);
        }

        // ---- A tile: 32 channels (this half), shifted coalesced reads ----
        const int yin = y - 1 + ky;
        const int xin = pixel - 1 + kx;
        const bool valid = ((unsigned)yin < (unsigned)HH) &&
                           ((unsigned)xin < (unsigned)WW);
        const float* xp0 = x + ((size_t)(b*CC)*DD + dd)*HW + yin*WW + xin;
#pragma unroll 2
        for (int g = 0; g < 4; g++) {
            float v[8];
#pragma unroll
            for (int k = 0; k < 8; k++) {
                int c = half*32 + g*8 + k;
                v[k] = valid ? xp0[(size_t)c*(DD*HW)] : 0.f;
            }
            uint32_t hi[4], lo[4];
            cvt_split8(v, hi, lo);
            uint32_t coff = (uint32_t)(((half*4 + g) ^ swrow) << 4);
            STS_V4(smem_u + CV_A_HI + arowb + coff, hi[0], hi[1], hi[2], hi[3]);
            STS_V4(smem_u + CV_A_LO + arowb + coff, lo[0], lo[1], lo[2], lo[3]);
        }

        __syncthreads();

        // ---- MMA ----
#pragma unroll
        for (int pass = 0; pass < 3; pass++) {
            const uint32_t Abase = smem_u + ((pass == 2) ? CV_A_LO : CV_A_HI);
            const uint32_t Bbase = smem_u + ((pass == 1) ? CV_B_LO : CV_B_HI);
#pragma unroll
            for (int ks = 0; ks < 4; ks++) {
                uint32_t a0, a1, a2, a3;
                {
                    int rr = wid*16 + arow_off;
                    uint32_t addr = Abase + (uint32_t)rr*128
                        + (uint32_t)((((ks*2 + achunk) ^ (rr & 7)) << 4));
                    LDMATRIX_X4(a0, a1, a2, a3, addr);
                }
#pragma unroll
                for (int np = 0; np < 2; np++) {
                    uint32_t b0, b1, b2, b3;
                    int nn = np*16 + brow_off;
                    uint32_t addr = Bbase + (uint32_t)nn*128
                        + (uint32_t)((((ks*2 + bchunk) ^ (nn & 7)) << 4));
                    LDMATRIX_X4(b0, b1, b2, b3, addr);
                    MMA_BF16(acc[np*2],   a0, a1, a2, a3, b0, b1);
                    MMA_BF16(acc[np*2+1], a0, a1, a2, a3, b2, b3);
                }
            }
        }
        __syncthreads();
    }

    // ---- epilogue: bias + sigmoid, write g_off / g_mask ----
    {
        int prow = wid*16 + (lane >> 2);
#pragma unroll
        for (int nt = 0; nt < 4; nt++) {
            int oc0 = nt*8 + 2*(lane & 3);
#pragma unroll
            for (int q = 0; q < 4; q++) {
                int oc = oc0 + (q & 1);
                int p  = prow + ((q >> 1) << 3);
                float v = acc[nt][q];
                int pixo = y*WW + p;
                if (oc < 18) {
                    g_off[((b*18 + oc)*DD + od)*HW + pixo] = v + ob[oc];
                } else if (oc < 27) {
                    float t = v + mb[oc - 18];
                    g_mask[((b*9 + oc - 18)*DD + od)*HW + pixo] =
                        2.f / (1.f + expf(-t));
                }
            }
        }
    }
}

// ---------------------------------------------------------------------------
// Kernel 2: deformable conv via mma.sync bf16 split-precision.
// 256 threads, 2 CTAs/SM. (pixel, half). Grid (128, 2, 4).
// ---------------------------------------------------------------------------
#define SM_A_HI   0
#define SM_A_LO   16384
#define SM_B_HI   32768
#define SM_B_LO   40960
#define SM_TOTAL  49152

__global__ __launch_bounds__(256, 2)
void deform_mma_kernel(const float* __restrict__ x, float* __restrict__ out)
{
    extern __shared__ char smem[];
    const uint32_t smem_u = smem_to_u32(smem);
    const int tid   = threadIdx.x;
    const int wid   = tid >> 5;
    const int lane  = tid & 31;
    const int pixel = tid & 127;
    const int half  = tid >> 7;
    const int y   = blockIdx.x;
    const int d   = blockIdx.y;
    const int b   = blockIdx.z;
    const int pix = y*WW + pixel;

    float acc[8][4];
#pragma unroll
    for (int nt = 0; nt < 8; nt++)
#pragma unroll
        for (int q = 0; q < 4; q++) acc[nt][q] = 0.f;

    const float* xbase = x + ((size_t)b*CC*DD + d) * HW;

    const int agrp = lane >> 3;
    const int arow_off = (lane & 7) + ((agrp & 1) << 3);
    const int achunk   = (agrp >> 1);
    const int brow_off = (lane & 7) + ((agrp >> 1) << 3);
    const int bchunk   = (agrp & 1);
    const uint32_t arowb = (uint32_t)pixel * 128;
    const int swrow = pixel & 7;

#pragma unroll 1
    for (int j = 0; j < 9; j++) {
        // ---- B tile copy ----
        {
            const uint4* sh = (const uint4*)(g_Bh[j]);
            const uint4* sl = (const uint4*)(g_Bl[j]);
#pragma unroll
            for (int it = 0; it < 2; it++) {
                int u = tid + 256*it;
                uint4 vh = sh[u];
                uint4 vl = sl[u];
                uint32_t dst = (uint32_t)u * 16;
                STS_V4(smem_u + SM_B_HI + dst, vh.x, vh.y, vh.z, vh.w);
                STS_V4(smem_u + SM_B_LO + dst, vl.x, vl.y, vl.z, vl.w);
            }
        }

        // ---- per-pixel sampling setup ----
        float dy = g_off[((b*18 + 2*j    )*DD + d)*HW + pix];
        float dx = g_off[((b*18 + 2*j + 1)*DD + d)*HW + pix];
        float m  = g_mask[((b*9 + j)*DD + d)*HW + pix];
        float py = (float)(y     - 1 + j/3) + dy;
        float px = (float)(pixel - 1 + j%3) + dx;
        float fy = floorf(py), fx = floorf(px);
        float ly = py - fy,    lx = px - fx;
        float hy = 1.f - ly,   hx = 1.f - lx;
        int iy0 = (int)fy, ix0 = (int)fx;
        int iy1 = iy0 + 1, ix1 = ix0 + 1;
        bool vy0 = ((unsigned)iy0 < (unsigned)HH);
        bool vy1 = ((unsigned)iy1 < (unsigned)HH);
        bool vx0 = ((unsigned)ix0 < (unsigned)WW);
        bool vx1 = ((unsigned)ix1 < (unsigned)WW);
        float a00 = (vy0 && vx0) ? hy*hx*m : 0.f;
        float a01 = (vy0 && vx1) ? hy*lx*m : 0.f;
        float a10 = (vy1 && vx0) ? ly*hx*m : 0.f;
        float a11 = (vy1 && vx1) ? ly*lx*m : 0.f;
        int yr0 = min(max(iy0, 0), HH-1)*WW;
        int yr1 = min(max(iy1, 0), HH-1)*WW;
        int xr0 = min(max(ix0, 0), WW-1);
        int xr1 = min(max(ix1, 0), WW-1);
        int o00 = yr0 + xr0, o01 = yr0 + xr1;
        int o10 = yr1 + xr0, o11 = yr1 + xr1;

        // ---- A tile: 32 channels (this half), coalesced channel-major ----
#pragma unroll 2
        for (int g = 0; g < 4; g++) {
            float v[8];
#pragma unroll
            for (int k = 0; k < 8; k++) {
                const float* xp = xbase + (size_t)(half*32 + g*8 + k)*(DD*HW);
                v[k] = a00*xp[o00] + a01*xp[o01] + a10*xp[o10] + a11*xp[o11];
            }
            uint32_t hi[4], lo[4];
            cvt_split8(v, hi, lo);
            uint32_t coff = (uint32_t)(((half*4 + g) ^ swrow) << 4);
            STS_V4(smem_u + SM_A_HI + arowb + coff, hi[0], hi[1], hi[2], hi[3]);
            STS_V4(smem_u + SM_A_LO + arowb + coff, lo[0], lo[1], lo[2], lo[3]);
        }

        __syncthreads();

        // ---- MMA ----
#pragma unroll
        for (int pass = 0; pass < 3; pass++) {
            const uint32_t Abase = smem_u + ((pass == 2) ? SM_A_LO : SM_A_HI);
            const uint32_t Bbase = smem_u + ((pass == 1) ? SM_B_LO : SM_B_HI);
#pragma unroll
            for (int ks = 0; ks < 4; ks++) {
                uint32_t a0, a1, a2, a3;
                {
                    int rr = wid*16 + arow_off;
                    uint32_t addr = Abase + (uint32_t)rr*128
                        + (uint32_t)((((ks*2 + achunk) ^ (rr & 7)) << 4));
                    LDMATRIX_X4(a0, a1, a2, a3, addr);
                }
#pragma unroll
                for (int np = 0; np < 4; np++) {
                    uint32_t b0, b1, b2, b3;
                    int nn = np*16 + brow_off;
                    uint32_t addr = Bbase + (uint32_t)nn*128
                        + (uint32_t)((((ks*2 + bchunk) ^ (nn & 7)) << 4));
                    LDMATRIX_X4(b0, b1, b2, b3, addr);
                    MMA_BF16(acc[np*2],   a0, a1, a2, a3, b0, b1);
                    MMA_BF16(acc[np*2+1], a0, a1, a2, a3, b2, b3);
                }
            }
        }
        __syncthreads();
    }

    // ---- epilogue ----
    {
        int xr = wid*16 + (lane >> 2);
        float* op0 = out + ((size_t)b*OO*DD + d)*HW + y*WW + xr;
#pragma unroll
        for (int nt = 0; nt < 8; nt++) {
            int oc = nt*8 + 2*(lane & 3);
            op0[(size_t)(oc  )*DD*HW    ] = acc[nt][0];
            op0[(size_t)(oc+1)*DD*HW    ] = acc[nt][1];
            op0[(size_t)(oc  )*DD*HW + 8] = acc[nt][2];
            op0[(size_t)(oc+1)*DD*HW + 8] = acc[nt][3];
        }
    }
}

// ---------------------------------------------------------------------------
// Launch
// ---------------------------------------------------------------------------
extern "C" void kernel_launch(void* const* d_in, const int* in_sizes, int n_in,
                              void* d_out, int out_size)
{
    const float* x  = (const float*)d_in[0];
    const float* ow = (const float*)d_in[1];
    const float* ob = (const float*)d_in[2];
    const float* mw = (const float*)d_in[3];
    const float* mb = (const float*)d_in[4];
    const float* w0 = (const float*)d_in[5];
    float* out = (float*)d_out;

    cudaFuncSetAttribute(deform_mma_kernel,
                         cudaFuncAttributeMaxDynamicSharedMemorySize, SM_TOTAL);
    cudaFuncSetAttribute(conv3d_mma_kernel,
                         cudaFuncAttributeMaxDynamicSharedMemorySize, CV_TOTAL);

    dim3 grid(HH, DD, BB);
    pack_w_kernel<<<120, 256>>>(w0, ow, mw);
    conv3d_mma_kernel<<<grid, 256, CV_TOTAL>>>(x, ob, mb);
    deform_mma_kernel<<<grid, 256, SM_TOTAL>>>(x, out);
}